// round 15
// baseline (speedup 1.0000x reference)
#include <cuda_runtime.h>
#include <cuda_fp16.h>
#include <cstdint>

#define NMAX 50000
#define EMAX 800000
#define KMAX 512
#define NTOTMAX 2048

// ======================= low-level helpers (sm_80-compatible PTX) ==========
__device__ __forceinline__ uint32_t smem_u32(const void* p) {
    uint32_t a;
    asm("{ .reg .u64 t; cvta.to.shared.u64 t, %1; cvt.u32.u64 %0, t; }" : "=r"(a) : "l"(p));
    return a;
}
__device__ __forceinline__ void cp16(uint32_t dst, const void* src, int srcsize) {
    asm volatile("cp.async.cg.shared.global [%0], [%1], 16, %2;"
                 :: "r"(dst), "l"(src), "r"(srcsize));
}
__device__ __forceinline__ void ldm_x4(uint32_t& r0, uint32_t& r1, uint32_t& r2, uint32_t& r3,
                                       uint32_t addr) {
    asm volatile("ldmatrix.sync.aligned.m8n8.x4.shared.b16 {%0,%1,%2,%3}, [%4];"
                 : "=r"(r0), "=r"(r1), "=r"(r2), "=r"(r3) : "r"(addr));
}
__device__ __forceinline__ void mma16816(float* c, const uint32_t* a, const uint32_t* b) {
    asm volatile("mma.sync.aligned.m16n8k16.row.col.f32.f16.f16.f32 "
                 "{%0,%1,%2,%3}, {%4,%5,%6,%7}, {%8,%9}, {%0,%1,%2,%3};"
                 : "+f"(c[0]), "+f"(c[1]), "+f"(c[2]), "+f"(c[3])
                 : "r"(a[0]), "r"(a[1]), "r"(a[2]), "r"(a[3]), "r"(b[0]), "r"(b[1]));
}

// ======================= scratch (device globals) =======================
__device__ float  g_q [NMAX * 512];
__device__ __half g_kh[NMAX * 512];
__device__ __half g_vh[NMAX * 512];
__device__ float  g_h0[NMAX * 512];
__device__ float  g_h1[NMAX * 512];
__device__ __half g_ahi[NMAX * KMAX];
__device__ __half g_alo[NMAX * KMAX];
__device__ __half g_whi[3 * NTOTMAX * KMAX];
__device__ __half g_wlo[3 * NTOTMAX * KMAX];
__device__ float g_biasf[3 * NTOTMAX];
__device__ int   g_rowptr[NMAX + 1];
__device__ int   g_cnt[NMAX];
__device__ int   g_cur[NMAX];
__device__ int   g_srcs[EMAX];
__device__ int   g_is64;

// ======================= edge dtype detection =======================
__global__ void detect_kernel(const int* __restrict__ w) {
    __shared__ int nz;
    if (threadIdx.x == 0) nz = 0;
    __syncthreads();
    if (w[2 * threadIdx.x + 1] != 0) atomicAdd(&nz, 1);
    __syncthreads();
    if (threadIdx.x == 0) g_is64 = (nz == 0) ? 1 : 0;
}
__device__ __forceinline__ int edge_at(const void* ei, long long idx, int is64) {
    return is64 ? (int)((const long long*)ei)[idx] : ((const int*)ei)[idx];
}

// ======================= CSR build =======================
__global__ void zero_int_kernel(int* __restrict__ p, int n) {
    int i = blockIdx.x * blockDim.x + threadIdx.x;
    if (i < n) p[i] = 0;
}
__global__ void hist_kernel(const void* __restrict__ ei, int* __restrict__ cnt, int E) {
    int e = blockIdx.x * blockDim.x + threadIdx.x;
    if (e < E) atomicAdd(&cnt[edge_at(ei, (long long)E + e, g_is64)], 1);
}
__global__ void scan_kernel(const int* __restrict__ cnt, int* __restrict__ rowptr,
                            int* __restrict__ cur, int n) {
    __shared__ int part[1024];
    const int t = threadIdx.x;
    const int chunk = (n + 1023) >> 10;
    int b = t * chunk; if (b > n) b = n;
    int e = b + chunk; if (e > n) e = n;
    int s = 0;
    for (int i = b; i < e; i++) s += cnt[i];
    part[t] = s;
    __syncthreads();
    if (t == 0) {
        int a = 0;
        for (int i = 0; i < 1024; i++) { int v = part[i]; part[i] = a; a += v; }
    }
    __syncthreads();
    int off = part[t];
    for (int i = b; i < e; i++) { rowptr[i] = off; cur[i] = off; off += cnt[i]; }
    if (t == 1023) rowptr[n] = off;
}
__global__ void scatter_kernel(const void* __restrict__ ei, int* __restrict__ cur,
                               int* __restrict__ srcs, int E) {
    int e = blockIdx.x * blockDim.x + threadIdx.x;
    if (e < E) {
        const int is64 = g_is64;
        int d = edge_at(ei, (long long)E + e, is64);
        int p = atomicAdd(&cur[d], 1);
        srcs[p] = edge_at(ei, e, is64);
    }
}

// ======================= weight prep: transpose + fp16 hi/lo split =========
struct WDesc { const float* W; const float* b; int K; int M; int layer; int off; };
struct WTable { WDesc d[12]; };

__global__ void prep_weights_kernel(WTable t, int y0, __half* __restrict__ whi,
                                    __half* __restrict__ wlo, float* __restrict__ biasf) {
    const WDesc w = t.d[y0 + blockIdx.y];
    const size_t base = (size_t)w.layer * NTOTMAX * KMAX;
    const int stride = gridDim.x * blockDim.x;
    for (int i = blockIdx.x * blockDim.x + threadIdx.x; i < w.M; i += stride)
        biasf[w.layer * NTOTMAX + w.off + i] = w.b[i];
    const int total = w.K * w.M;
    for (int i = blockIdx.x * blockDim.x + threadIdx.x; i < total; i += stride) {
        int k = i / w.M, m = i % w.M;
        float v = w.W[i];
        __half hi = __float2half(v);
        float lo = v - __half2float(hi);
        size_t dst = base + (size_t)(w.off + m) * w.K + k;
        whi[dst] = hi;
        wlo[dst] = __float2half(lo);
    }
}

// ======================= activation fp16 hi/lo split (input x only) ========
__global__ void split_act_kernel(const float* __restrict__ x, __half* __restrict__ hi,
                                 __half* __restrict__ lo, int total) {
    int i = blockIdx.x * blockDim.x + threadIdx.x;
    if (i < total) {
        float v = x[i];
        __half h = __float2half(v);
        hi[i] = h;
        lo[i] = __float2half(v - __half2float(h));
    }
}

// ======================= HMMA GEMM: C[N, ntot] = A @ Wt^T + bias ===========
// fp16 split in register accumulators. Per-column-tile pass count:
//   3-pass: Ahi*Bhi + Alo*Bhi + Ahi*Blo   (full precision)
//   2-pass: Ahi*Bhi + Alo*Bhi             (lp2: skip tiles — exact x, fp16 W)
//   1-pass: Ahi*Bhi                       (lp1: q,k,v — logits / fp16-stored)
// Unneeded Alo/Blo tile loads are skipped per level.
// kc-outer / pass-inner, double-buffered 4-region SMEM, one wait+sync per kc.
// CTA tile 128x128, BK=32, 8 warps (2x4), warp tile 64x32.
#define STG_BYTES 10240                 /* 128 rows * 80B padded */
#define SMEM_TOT  (8 * STG_BYTES)       /* 4 tensors x 2 slots = 81920 */

struct OutSpec { void* out[4]; int half_mask; int cpo; };

__global__ void __launch_bounds__(256, 2)
gemm_mma_kernel(const __half* __restrict__ Ahi, const __half* __restrict__ Alo,
                const __half* __restrict__ Whi, const __half* __restrict__ Wlo,
                const float* __restrict__ biasf, OutSpec os, int Nrows, int K,
                uint32_t lp2_mask, uint32_t lp1_mask)
{
    extern __shared__ char smem[];
    const uint32_t sb = smem_u32(smem);
    const int tid = threadIdx.x, lane = tid & 31, wid = tid >> 5;
    const int wm = wid & 1, wn = wid >> 1;
    const int m0 = blockIdx.y * 128, n0 = blockIdx.x * 128;
    const int KT = K / 32;
    const int npass = ((lp1_mask >> blockIdx.x) & 1u) ? 1
                    : (((lp2_mask >> blockIdx.x) & 1u) ? 2 : 3);

    float acc[4][4][4];
#pragma unroll
    for (int a = 0; a < 4; a++)
#pragma unroll
        for (int b = 0; b < 4; b++)
#pragma unroll
            for (int c = 0; c < 4; c++) acc[a][b][c] = 0.f;

    const int r0 = tid >> 2, c0 = tid & 3;
    const int r1 = r0 + 64;

    // region(tensor, slot) base: tensor 0=Ahi 1=Alo 2=Bhi 3=Blo
    auto issueKC = [&](int kc) {
        const int slot = kc & 1;
        const int koff = kc * 32;
        int ar0 = m0 + r0; bool v0 = ar0 < Nrows; if (!v0) ar0 = 0;
        int ar1 = m0 + r1; bool v1 = ar1 < Nrows; if (!v1) ar1 = 0;
        const uint32_t sAhi = sb + (0 * 2 + slot) * STG_BYTES;
        const uint32_t sAlo = sb + (1 * 2 + slot) * STG_BYTES;
        const uint32_t sBhi = sb + (2 * 2 + slot) * STG_BYTES;
        const uint32_t sBlo = sb + (3 * 2 + slot) * STG_BYTES;
        const uint32_t ro0 = r0 * 80 + c0 * 16, ro1 = r1 * 80 + c0 * 16;
        cp16(sAhi + ro0, Ahi + (size_t)ar0 * K + koff + c0 * 8, v0 ? 16 : 0);
        cp16(sAhi + ro1, Ahi + (size_t)ar1 * K + koff + c0 * 8, v1 ? 16 : 0);
        if (npass >= 2) {
            cp16(sAlo + ro0, Alo + (size_t)ar0 * K + koff + c0 * 8, v0 ? 16 : 0);
            cp16(sAlo + ro1, Alo + (size_t)ar1 * K + koff + c0 * 8, v1 ? 16 : 0);
        }
        cp16(sBhi + ro0, Whi + (size_t)(n0 + r0) * K + koff + c0 * 8, 16);
        cp16(sBhi + ro1, Whi + (size_t)(n0 + r1) * K + koff + c0 * 8, 16);
        if (npass == 3) {
            cp16(sBlo + ro0, Wlo + (size_t)(n0 + r0) * K + koff + c0 * 8, 16);
            cp16(sBlo + ro1, Wlo + (size_t)(n0 + r1) * K + koff + c0 * 8, 16);
        }
    };

    // per-warp ldmatrix local offsets (within a region)
    const uint32_t aLoc = (uint32_t)((wm * 64 + (lane & 15)) * 80 + (lane >> 4) * 16);
    const uint32_t bLoc = (uint32_t)((wn * 32 + (lane & 7) + ((lane >> 4) << 3)) * 80
                                     + ((lane >> 3) & 1) * 16);

    issueKC(0);
    asm volatile("cp.async.commit_group;" ::: "memory");

    for (int kc = 0; kc < KT; kc++) {
        asm volatile("cp.async.wait_group 0;" ::: "memory");
        __syncthreads();
        if (kc + 1 < KT) {
            issueKC(kc + 1);
            asm volatile("cp.async.commit_group;" ::: "memory");
        }
        const int slot = kc & 1;
#pragma unroll
        for (int pass = 0; pass < 3; pass++) {
            if (pass >= npass) break;
            const int aR = (pass == 1) ? 1 : 0;   // Alo on pass 1
            const int bR = (pass == 2) ? 3 : 2;   // Blo on pass 2
            const uint32_t aBase = sb + (uint32_t)(aR * 2 + slot) * STG_BYTES + aLoc;
            const uint32_t bBase = sb + (uint32_t)(bR * 2 + slot) * STG_BYTES + bLoc;
#pragma unroll
            for (int ks = 0; ks < 2; ks++) {
                uint32_t a[4][4], b[2][4];
#pragma unroll
                for (int mi = 0; mi < 4; mi++)
                    ldm_x4(a[mi][0], a[mi][1], a[mi][2], a[mi][3],
                           aBase + mi * 16 * 80 + ks * 32);
#pragma unroll
                for (int nj = 0; nj < 2; nj++)
                    ldm_x4(b[nj][0], b[nj][1], b[nj][2], b[nj][3],
                           bBase + nj * 16 * 80 + ks * 32);
#pragma unroll
                for (int mi = 0; mi < 4; mi++)
#pragma unroll
                    for (int ni = 0; ni < 4; ni++)
                        mma16816(acc[mi][ni], a[mi], &b[ni >> 1][(ni & 1) * 2]);
            }
        }
    }

    const int erow = lane >> 2, ecol = (lane & 3) * 2;
#pragma unroll
    for (int mi = 0; mi < 4; mi++) {
#pragma unroll
        for (int half = 0; half < 2; half++) {
            const int gr = m0 + wm * 64 + mi * 16 + erow + half * 8;
            if (gr >= Nrows) continue;
#pragma unroll
            for (int ni = 0; ni < 4; ni++) {
                const int gc = n0 + wn * 32 + ni * 8 + ecol;
                const int slot = gc / os.cpo;
                const int loc  = gc % os.cpo;
                float ox = acc[mi][ni][half * 2 + 0] + biasf[gc + 0];
                float oy = acc[mi][ni][half * 2 + 1] + biasf[gc + 1];
                if (os.half_mask & (1 << slot)) {
                    __half2 h2 = __floats2half2_rn(ox, oy);
                    *reinterpret_cast<__half2*>((__half*)os.out[slot] + (size_t)gr * os.cpo + loc) = h2;
                } else {
                    float2 o = make_float2(ox, oy);
                    *reinterpret_cast<float2*>((float*)os.out[slot] + (size_t)gr * os.cpo + loc) = o;
                }
            }
        }
    }
}

// ======================= per-node attention aggregation =======================
template<int PER>
__device__ __forceinline__ void vloadf(float* r, const float* __restrict__ p) {
#pragma unroll
    for (int i = 0; i < PER / 2; i++) {
        float2 t = reinterpret_cast<const float2*>(p)[i];
        r[2 * i + 0] = t.x; r[2 * i + 1] = t.y;
    }
}
template<int PER>
__device__ __forceinline__ void vloadh(float* r, const __half* __restrict__ p) {
    if constexpr (PER % 8 == 0) {
#pragma unroll
        for (int i = 0; i < PER / 8; i++) {
            uint4 t = reinterpret_cast<const uint4*>(p)[i];
            const __half2* h = reinterpret_cast<const __half2*>(&t);
#pragma unroll
            for (int j = 0; j < 4; j++) {
                float2 f = __half22float2(h[j]);
                r[i * 8 + j * 2 + 0] = f.x;
                r[i * 8 + j * 2 + 1] = f.y;
            }
        }
    } else {
        float2 f = __half22float2(*reinterpret_cast<const __half2*>(p));
        r[0] = f.x; r[1] = f.y;
    }
}

// One warp per destination node; 4-edge batch with K AND V gathered upfront as
// raw uint4 (MLP=16/lane, no false dependency of v-loads on softmax), lazy
// conversion at use. Online softmax; optional fused fp16 hi/lo split epilogue.
template<int HEADS, int CH, bool RELU, bool SPLIT>
__global__ void __launch_bounds__(256)
gat_agg_kernel(const float* __restrict__ Q, const __half* __restrict__ Kf,
               const __half* __restrict__ V,
               const int* __restrict__ rowptr, const int* __restrict__ srcs,
               float* __restrict__ out,
               __half* __restrict__ hi, __half* __restrict__ lo, int n)
{
    constexpr int NCH = HEADS * CH;
    constexpr int PER = NCH / 32;
    constexpr int RW  = CH / PER;
    const int lane = threadIdx.x & 31;
    const int node = blockIdx.x * (blockDim.x >> 5) + (threadIdx.x >> 5);
    if (node >= n) return;

    const float scale = rsqrtf((float)CH);
    const size_t base = (size_t)node * NCH + lane * PER;

    float qv[PER], acc[PER];
    vloadf<PER>(qv, Q + base);
#pragma unroll
    for (int i = 0; i < PER; i++) acc[i] = 0.f;

    float m = __int_as_float(0xff800000);
    float s = 0.f;

    const int e0 = rowptr[node];
    const int e1 = rowptr[node + 1];
    int e = e0;

    if constexpr (PER % 8 == 0) {
        constexpr int NU = PER / 8;            // uint4s per row slice
        for (; e + 4 <= e1; e += 4) {
            size_t b[4];
#pragma unroll
            for (int j = 0; j < 4; j++)
                b[j] = (size_t)srcs[e + j] * NCH + lane * PER;

            // gather K and V for all 4 edges upfront (raw, no conversion)
            uint4 ku[4][NU], vu[4][NU];
#pragma unroll
            for (int j = 0; j < 4; j++) {
#pragma unroll
                for (int i = 0; i < NU; i++) {
                    ku[j][i] = reinterpret_cast<const uint4*>(Kf + b[j])[i];
                    vu[j][i] = reinterpret_cast<const uint4*>(V  + b[j])[i];
                }
            }

            float p[4];
#pragma unroll
            for (int j = 0; j < 4; j++) {
                float d = 0.f;
#pragma unroll
                for (int i = 0; i < NU; i++) {
                    const __half2* h = reinterpret_cast<const __half2*>(&ku[j][i]);
#pragma unroll
                    for (int t = 0; t < 4; t++) {
                        float2 f = __half22float2(h[t]);
                        d = fmaf(qv[i * 8 + t * 2 + 0], f.x, d);
                        d = fmaf(qv[i * 8 + t * 2 + 1], f.y, d);
                    }
                }
                p[j] = d;
            }
#pragma unroll
            for (int off = RW >> 1; off > 0; off >>= 1) {
#pragma unroll
                for (int j = 0; j < 4; j++)
                    p[j] += __shfl_xor_sync(0xffffffffu, p[j], off);
            }
            float w[4];
            const float a0 = p[0] * scale, a1 = p[1] * scale;
            const float a2 = p[2] * scale, a3 = p[3] * scale;
            const float mn = fmaxf(fmaxf(m, fmaxf(a0, a1)), fmaxf(a2, a3));
            const float corr = __expf(m - mn);
            w[0] = __expf(a0 - mn); w[1] = __expf(a1 - mn);
            w[2] = __expf(a2 - mn); w[3] = __expf(a3 - mn);
            s = s * corr + (w[0] + w[1]) + (w[2] + w[3]);

#pragma unroll
            for (int i = 0; i < PER; i++) acc[i] *= corr;
#pragma unroll
            for (int j = 0; j < 4; j++) {
                const float wj = w[j];
#pragma unroll
                for (int i = 0; i < NU; i++) {
                    const __half2* h = reinterpret_cast<const __half2*>(&vu[j][i]);
#pragma unroll
                    for (int t = 0; t < 4; t++) {
                        float2 f = __half22float2(h[t]);
                        acc[i * 8 + t * 2 + 0] = fmaf(wj, f.x, acc[i * 8 + t * 2 + 0]);
                        acc[i * 8 + t * 2 + 1] = fmaf(wj, f.y, acc[i * 8 + t * 2 + 1]);
                    }
                }
            }
            m = mn;
        }
    }
    for (; e < e1; e++) {
        const int sn = srcs[e];
        const size_t sbx = (size_t)sn * NCH + lane * PER;
        float kv[PER], vv[PER];
        vloadh<PER>(kv, Kf + sbx);
        vloadh<PER>(vv, V  + sbx);
        float part = 0.f;
#pragma unroll
        for (int i = 0; i < PER; i++) part = fmaf(qv[i], kv[i], part);
#pragma unroll
        for (int off = RW >> 1; off > 0; off >>= 1)
            part += __shfl_xor_sync(0xffffffffu, part, off);
        const float alpha = part * scale;
        const float mn = fmaxf(m, alpha);
        const float corr = __expf(m - mn);
        const float w = __expf(alpha - mn);
        s = s * corr + w;
#pragma unroll
        for (int i = 0; i < PER; i++) acc[i] = fmaf(acc[i], corr, w * vv[i]);
        m = mn;
    }

    const float inv = 1.f / (s + 1e-16f);
#pragma unroll
    for (int i = 0; i < PER; i++) {
        float o = out[base + i] + acc[i] * inv;
        if (RELU) o = fmaxf(o, 0.f);
        out[base + i] = o;
        if (SPLIT) {
            __half h = __float2half(o);
            hi[base + i] = h;
            lo[base + i] = __float2half(o - __half2float(h));
        }
    }
}

// ======================= host orchestration =======================
extern "C" void kernel_launch(void* const* d_in, const int* in_sizes, int n_in,
                              void* d_out, int out_size)
{
    const float* x  = (const float*)d_in[0];
    const void*  ei = d_in[1];
    const int N = in_sizes[0] / 128;
    const int E = in_sizes[1] / 2;

    const float* P[24];
    for (int i = 0; i < 24; i++) P[i] = (const float*)d_in[2 + i];

    float *q, *h0, *h1, *biasf;
    __half *kh, *vh;
    __half *ahi, *alo, *whi, *wlo;
    int *rowptr, *cnt, *cur, *srcs;
    cudaGetSymbolAddress((void**)&q,  g_q);
    cudaGetSymbolAddress((void**)&kh, g_kh);
    cudaGetSymbolAddress((void**)&vh, g_vh);
    cudaGetSymbolAddress((void**)&h0, g_h0);
    cudaGetSymbolAddress((void**)&h1, g_h1);
    cudaGetSymbolAddress((void**)&ahi, g_ahi);
    cudaGetSymbolAddress((void**)&alo, g_alo);
    cudaGetSymbolAddress((void**)&whi, g_whi);
    cudaGetSymbolAddress((void**)&wlo, g_wlo);
    cudaGetSymbolAddress((void**)&biasf, g_biasf);
    cudaGetSymbolAddress((void**)&rowptr, g_rowptr);
    cudaGetSymbolAddress((void**)&cnt, g_cnt);
    cudaGetSymbolAddress((void**)&cur, g_cur);
    cudaGetSymbolAddress((void**)&srcs, g_srcs);

    cudaFuncSetAttribute(gemm_mma_kernel, cudaFuncAttributeMaxDynamicSharedMemorySize, SMEM_TOT);

    // side stream + events (created once; never allocates device memory)
    static cudaStream_t s2 = nullptr;
    static cudaEvent_t evA = nullptr, evB = nullptr, evC = nullptr;
    if (!s2) {
        cudaStreamCreateWithFlags(&s2, cudaStreamNonBlocking);
        cudaEventCreateWithFlags(&evA, cudaEventDisableTiming);
        cudaEventCreateWithFlags(&evB, cudaEventDisableTiming);
        cudaEventCreateWithFlags(&evC, cudaEventDisableTiming);
    }

    const int TB = 256;
    float* out = (float*)d_out;

    WTable wt;
    const int Ks[3] = {128, 512, 512};
    const int Ms[3] = {512, 512, 64};
    for (int l = 0; l < 3; l++)
        for (int j = 0; j < 4; j++) {
            wt.d[l * 4 + j].W = P[l * 8 + j * 2];
            wt.d[l * 4 + j].b = P[l * 8 + j * 2 + 1];
            wt.d[l * 4 + j].K = Ks[l];
            wt.d[l * 4 + j].M = Ms[l];
            wt.d[l * 4 + j].layer = l;
            wt.d[l * 4 + j].off = j * Ms[l];
        }

    // layers 0/1: q,k,v tiles (0-11) 1-pass; skip tiles (12-15) 2-pass
    const uint32_t LP2_01 = 0xF000u;
    const uint32_t LP1_01 = 0x0FFFu;
    // layer 2 (2 tiles of 128): tile 0 = q+k -> 1-pass; tile 1 = v+skip -> 3-pass
    const uint32_t LP2_2 = 0x0u;
    const uint32_t LP1_2 = 0x1u;

    // ---- fork: CSR build + layer-1/2 weight prep on s2 ----
    detect_kernel<<<1, 128>>>((const int*)ei);
    cudaEventRecord(evA, 0);
    cudaStreamWaitEvent(s2, evA, 0);
    zero_int_kernel<<<(N + TB - 1) / TB, TB, 0, s2>>>(cnt, N);
    hist_kernel<<<(E + TB - 1) / TB, TB, 0, s2>>>(ei, cnt, E);
    scan_kernel<<<1, 1024, 0, s2>>>(cnt, rowptr, cur, N);
    scatter_kernel<<<(E + TB - 1) / TB, TB, 0, s2>>>(ei, cur, srcs, E);
    cudaEventRecord(evB, s2);
    prep_weights_kernel<<<dim3(64, 8), TB, 0, s2>>>(wt, 4, whi, wlo, biasf);
    cudaEventRecord(evC, s2);

    // main stream: layer-0 prep + GEMM-0
    prep_weights_kernel<<<dim3(64, 4), TB>>>(wt, 0, whi, wlo, biasf);
    split_act_kernel<<<(N * 128 + TB - 1) / TB, TB>>>(x, ahi, alo, N * 128);

    const int mtiles = (N + 127) / 128;
    OutSpec os0;
    os0.out[0] = q; os0.out[1] = kh; os0.out[2] = vh; os0.out[3] = h0;
    os0.half_mask = 0b0110; os0.cpo = 512;
    gemm_mma_kernel<<<dim3(2048 / 128, mtiles), 256, SMEM_TOT>>>(
        ahi, alo, whi, wlo, biasf, os0, N, 128, LP2_01, LP1_01);

    cudaStreamWaitEvent(0, evB, 0);   // CSR ready before aggregation

    const int aggBlocks = (N + 7) / 8;
    gat_agg_kernel<8, 64, true, true><<<aggBlocks, 256>>>(
        q, kh, vh, rowptr, srcs, h0, ahi, alo, N);

    cudaStreamWaitEvent(0, evC, 0);   // layer-1/2 weights ready

    // ---- layer 1 ----
    OutSpec os1;
    os1.out[0] = q; os1.out[1] = kh; os1.out[2] = vh; os1.out[3] = h1;
    os1.half_mask = 0b0110; os1.cpo = 512;
    gemm_mma_kernel<<<dim3(2048 / 128, mtiles), 256, SMEM_TOT>>>(
        ahi, alo, whi + (size_t)1 * NTOTMAX * KMAX, wlo + (size_t)1 * NTOTMAX * KMAX,
        biasf + NTOTMAX, os1, N, 512, LP2_01, LP1_01);
    gat_agg_kernel<8, 64, true, true><<<aggBlocks, 256>>>(
        q, kh, vh, rowptr, srcs, h1, ahi, alo, N);

    // ---- layer 2 (heads=1, ch=64) ----
    OutSpec os2;
    os2.out[0] = q; os2.out[1] = kh; os2.out[2] = vh; os2.out[3] = out;
    os2.half_mask = 0b0110; os2.cpo = 64;
    gemm_mma_kernel<<<dim3(256 / 128, mtiles), 256, SMEM_TOT>>>(
        ahi, alo, whi + (size_t)2 * NTOTMAX * KMAX, wlo + (size_t)2 * NTOTMAX * KMAX,
        biasf + 2 * NTOTMAX, os2, N, 512, LP2_2, LP1_2);
    gat_agg_kernel<1, 64, false, false><<<aggBlocks, 256>>>(
        q, kh, vh, rowptr, srcs, out, nullptr, nullptr, N);
}

// round 17
// speedup vs baseline: 1.5839x; 1.5839x over previous
#include <cuda_runtime.h>
#include <cuda_fp16.h>
#include <cstdint>

#define NMAX 50000
#define EMAX 800000
#define KMAX 512
#define NTOTMAX 2048

// ======================= low-level helpers (sm_80-compatible PTX) ==========
__device__ __forceinline__ uint32_t smem_u32(const void* p) {
    uint32_t a;
    asm("{ .reg .u64 t; cvta.to.shared.u64 t, %1; cvt.u32.u64 %0, t; }" : "=r"(a) : "l"(p));
    return a;
}
__device__ __forceinline__ void cp16(uint32_t dst, const void* src, int srcsize) {
    asm volatile("cp.async.cg.shared.global [%0], [%1], 16, %2;"
                 :: "r"(dst), "l"(src), "r"(srcsize));
}
__device__ __forceinline__ void ldm_x4(uint32_t& r0, uint32_t& r1, uint32_t& r2, uint32_t& r3,
                                       uint32_t addr) {
    asm volatile("ldmatrix.sync.aligned.m8n8.x4.shared.b16 {%0,%1,%2,%3}, [%4];"
                 : "=r"(r0), "=r"(r1), "=r"(r2), "=r"(r3) : "r"(addr));
}
__device__ __forceinline__ void mma16816(float* c, const uint32_t* a, const uint32_t* b) {
    asm volatile("mma.sync.aligned.m16n8k16.row.col.f32.f16.f16.f32 "
                 "{%0,%1,%2,%3}, {%4,%5,%6,%7}, {%8,%9}, {%0,%1,%2,%3};"
                 : "+f"(c[0]), "+f"(c[1]), "+f"(c[2]), "+f"(c[3])
                 : "r"(a[0]), "r"(a[1]), "r"(a[2]), "r"(a[3]), "r"(b[0]), "r"(b[1]));
}

// ======================= scratch (device globals) =======================
__device__ __half g_qh[NMAX * 512];
__device__ __half g_kh[NMAX * 512];
__device__ __half g_vh[NMAX * 512];
__device__ float  g_h0[NMAX * 512];
__device__ float  g_h1[NMAX * 512];
__device__ __half g_ahi[NMAX * KMAX];
__device__ __half g_alo[NMAX * KMAX];
__device__ __half g_whi[3 * NTOTMAX * KMAX];
__device__ __half g_wlo[3 * NTOTMAX * KMAX];
__device__ float g_biasf[3 * NTOTMAX];
__device__ int   g_rowptr[NMAX + 1];
__device__ int   g_cnt[NMAX];
__device__ int   g_cur[NMAX];
__device__ int   g_srcs[EMAX];
__device__ int   g_is64;

// ======================= edge dtype detection =======================
__global__ void detect_kernel(const int* __restrict__ w) {
    __shared__ int nz;
    if (threadIdx.x == 0) nz = 0;
    __syncthreads();
    if (w[2 * threadIdx.x + 1] != 0) atomicAdd(&nz, 1);
    __syncthreads();
    if (threadIdx.x == 0) g_is64 = (nz == 0) ? 1 : 0;
}
__device__ __forceinline__ int edge_at(const void* ei, long long idx, int is64) {
    return is64 ? (int)((const long long*)ei)[idx] : ((const int*)ei)[idx];
}

// ======================= CSR build =======================
__global__ void zero_int_kernel(int* __restrict__ p, int n) {
    int i = blockIdx.x * blockDim.x + threadIdx.x;
    if (i < n) p[i] = 0;
}
__global__ void hist_kernel(const void* __restrict__ ei, int* __restrict__ cnt, int E) {
    int e = blockIdx.x * blockDim.x + threadIdx.x;
    if (e < E) atomicAdd(&cnt[edge_at(ei, (long long)E + e, g_is64)], 1);
}
__global__ void scan_kernel(const int* __restrict__ cnt, int* __restrict__ rowptr,
                            int* __restrict__ cur, int n) {
    __shared__ int part[1024];
    const int t = threadIdx.x;
    const int chunk = (n + 1023) >> 10;
    int b = t * chunk; if (b > n) b = n;
    int e = b + chunk; if (e > n) e = n;
    int s = 0;
    for (int i = b; i < e; i++) s += cnt[i];
    part[t] = s;
    __syncthreads();
    if (t == 0) {
        int a = 0;
        for (int i = 0; i < 1024; i++) { int v = part[i]; part[i] = a; a += v; }
    }
    __syncthreads();
    int off = part[t];
    for (int i = b; i < e; i++) { rowptr[i] = off; cur[i] = off; off += cnt[i]; }
    if (t == 1023) rowptr[n] = off;
}
__global__ void scatter_kernel(const void* __restrict__ ei, int* __restrict__ cur,
                               int* __restrict__ srcs, int E) {
    int e = blockIdx.x * blockDim.x + threadIdx.x;
    if (e < E) {
        const int is64 = g_is64;
        int d = edge_at(ei, (long long)E + e, is64);
        int p = atomicAdd(&cur[d], 1);
        srcs[p] = edge_at(ei, e, is64);
    }
}

// ======================= weight prep: transpose + fp16 hi/lo split =========
struct WDesc { const float* W; const float* b; int K; int M; int layer; int off; };
struct WTable { WDesc d[12]; };

__global__ void prep_weights_kernel(WTable t, int y0, __half* __restrict__ whi,
                                    __half* __restrict__ wlo, float* __restrict__ biasf) {
    const WDesc w = t.d[y0 + blockIdx.y];
    const size_t base = (size_t)w.layer * NTOTMAX * KMAX;
    const int stride = gridDim.x * blockDim.x;
    for (int i = blockIdx.x * blockDim.x + threadIdx.x; i < w.M; i += stride)
        biasf[w.layer * NTOTMAX + w.off + i] = w.b[i];
    const int total = w.K * w.M;
    for (int i = blockIdx.x * blockDim.x + threadIdx.x; i < total; i += stride) {
        int k = i / w.M, m = i % w.M;
        float v = w.W[i];
        __half hi = __float2half(v);
        float lo = v - __half2float(hi);
        size_t dst = base + (size_t)(w.off + m) * w.K + k;
        whi[dst] = hi;
        wlo[dst] = __float2half(lo);
    }
}

// ======================= activation fp16 hi/lo split (input x only) ========
__global__ void split_act_kernel(const float* __restrict__ x, __half* __restrict__ hi,
                                 __half* __restrict__ lo, int total) {
    int i = blockIdx.x * blockDim.x + threadIdx.x;
    if (i < total) {
        float v = x[i];
        __half h = __float2half(v);
        hi[i] = h;
        lo[i] = __float2half(v - __half2float(h));
    }
}

// ======================= HMMA GEMM: C[N, ntot] = A @ Wt^T + bias ===========
// fp16 split in register accumulators. Per-column-tile pass count:
//   3-pass: Ahi*Bhi + Alo*Bhi + Ahi*Blo   (full precision)
//   2-pass: Ahi*Bhi + Alo*Bhi             (lp2: skip tiles — exact x, fp16 W)
//   1-pass: Ahi*Bhi                       (lp1: q,k,v — logits / fp16-stored)
// Unneeded Alo/Blo tile loads are skipped per level.
// kc-outer / pass-inner, double-buffered 4-region SMEM, one wait+sync per kc.
// CTA tile 128x128, BK=32, 8 warps (2x4), warp tile 64x32.
#define STG_BYTES 10240                 /* 128 rows * 80B padded */
#define SMEM_TOT  (8 * STG_BYTES)       /* 4 tensors x 2 slots = 81920 */

struct OutSpec { void* out[4]; int half_mask; int cpo; };

__global__ void __launch_bounds__(256, 2)
gemm_mma_kernel(const __half* __restrict__ Ahi, const __half* __restrict__ Alo,
                const __half* __restrict__ Whi, const __half* __restrict__ Wlo,
                const float* __restrict__ biasf, OutSpec os, int Nrows, int K,
                uint32_t lp2_mask, uint32_t lp1_mask)
{
    extern __shared__ char smem[];
    const uint32_t sb = smem_u32(smem);
    const int tid = threadIdx.x, lane = tid & 31, wid = tid >> 5;
    const int wm = wid & 1, wn = wid >> 1;
    const int m0 = blockIdx.y * 128, n0 = blockIdx.x * 128;
    const int KT = K / 32;
    const int npass = ((lp1_mask >> blockIdx.x) & 1u) ? 1
                    : (((lp2_mask >> blockIdx.x) & 1u) ? 2 : 3);

    float acc[4][4][4];
#pragma unroll
    for (int a = 0; a < 4; a++)
#pragma unroll
        for (int b = 0; b < 4; b++)
#pragma unroll
            for (int c = 0; c < 4; c++) acc[a][b][c] = 0.f;

    const int r0 = tid >> 2, c0 = tid & 3;
    const int r1 = r0 + 64;

    // region(tensor, slot) base: tensor 0=Ahi 1=Alo 2=Bhi 3=Blo
    auto issueKC = [&](int kc) {
        const int slot = kc & 1;
        const int koff = kc * 32;
        int ar0 = m0 + r0; bool v0 = ar0 < Nrows; if (!v0) ar0 = 0;
        int ar1 = m0 + r1; bool v1 = ar1 < Nrows; if (!v1) ar1 = 0;
        const uint32_t sAhi = sb + (0 * 2 + slot) * STG_BYTES;
        const uint32_t sAlo = sb + (1 * 2 + slot) * STG_BYTES;
        const uint32_t sBhi = sb + (2 * 2 + slot) * STG_BYTES;
        const uint32_t sBlo = sb + (3 * 2 + slot) * STG_BYTES;
        const uint32_t ro0 = r0 * 80 + c0 * 16, ro1 = r1 * 80 + c0 * 16;
        cp16(sAhi + ro0, Ahi + (size_t)ar0 * K + koff + c0 * 8, v0 ? 16 : 0);
        cp16(sAhi + ro1, Ahi + (size_t)ar1 * K + koff + c0 * 8, v1 ? 16 : 0);
        if (npass >= 2) {
            cp16(sAlo + ro0, Alo + (size_t)ar0 * K + koff + c0 * 8, v0 ? 16 : 0);
            cp16(sAlo + ro1, Alo + (size_t)ar1 * K + koff + c0 * 8, v1 ? 16 : 0);
        }
        cp16(sBhi + ro0, Whi + (size_t)(n0 + r0) * K + koff + c0 * 8, 16);
        cp16(sBhi + ro1, Whi + (size_t)(n0 + r1) * K + koff + c0 * 8, 16);
        if (npass == 3) {
            cp16(sBlo + ro0, Wlo + (size_t)(n0 + r0) * K + koff + c0 * 8, 16);
            cp16(sBlo + ro1, Wlo + (size_t)(n0 + r1) * K + koff + c0 * 8, 16);
        }
    };

    // per-warp ldmatrix local offsets (within a region)
    const uint32_t aLoc = (uint32_t)((wm * 64 + (lane & 15)) * 80 + (lane >> 4) * 16);
    const uint32_t bLoc = (uint32_t)((wn * 32 + (lane & 7) + ((lane >> 4) << 3)) * 80
                                     + ((lane >> 3) & 1) * 16);

    issueKC(0);
    asm volatile("cp.async.commit_group;" ::: "memory");

    for (int kc = 0; kc < KT; kc++) {
        asm volatile("cp.async.wait_group 0;" ::: "memory");
        __syncthreads();
        if (kc + 1 < KT) {
            issueKC(kc + 1);
            asm volatile("cp.async.commit_group;" ::: "memory");
        }
        const int slot = kc & 1;
#pragma unroll
        for (int pass = 0; pass < 3; pass++) {
            if (pass >= npass) break;
            const int aR = (pass == 1) ? 1 : 0;   // Alo on pass 1
            const int bR = (pass == 2) ? 3 : 2;   // Blo on pass 2
            const uint32_t aBase = sb + (uint32_t)(aR * 2 + slot) * STG_BYTES + aLoc;
            const uint32_t bBase = sb + (uint32_t)(bR * 2 + slot) * STG_BYTES + bLoc;
#pragma unroll
            for (int ks = 0; ks < 2; ks++) {
                uint32_t a[4][4], b[2][4];
#pragma unroll
                for (int mi = 0; mi < 4; mi++)
                    ldm_x4(a[mi][0], a[mi][1], a[mi][2], a[mi][3],
                           aBase + mi * 16 * 80 + ks * 32);
#pragma unroll
                for (int nj = 0; nj < 2; nj++)
                    ldm_x4(b[nj][0], b[nj][1], b[nj][2], b[nj][3],
                           bBase + nj * 16 * 80 + ks * 32);
#pragma unroll
                for (int mi = 0; mi < 4; mi++)
#pragma unroll
                    for (int ni = 0; ni < 4; ni++)
                        mma16816(acc[mi][ni], a[mi], &b[ni >> 1][(ni & 1) * 2]);
            }
        }
    }

    const int erow = lane >> 2, ecol = (lane & 3) * 2;
#pragma unroll
    for (int mi = 0; mi < 4; mi++) {
#pragma unroll
        for (int half = 0; half < 2; half++) {
            const int gr = m0 + wm * 64 + mi * 16 + erow + half * 8;
            if (gr >= Nrows) continue;
#pragma unroll
            for (int ni = 0; ni < 4; ni++) {
                const int gc = n0 + wn * 32 + ni * 8 + ecol;
                const int slot = gc / os.cpo;
                const int loc  = gc % os.cpo;
                float ox = acc[mi][ni][half * 2 + 0] + biasf[gc + 0];
                float oy = acc[mi][ni][half * 2 + 1] + biasf[gc + 1];
                if (os.half_mask & (1 << slot)) {
                    __half2 h2 = __floats2half2_rn(ox, oy);
                    *reinterpret_cast<__half2*>((__half*)os.out[slot] + (size_t)gr * os.cpo + loc) = h2;
                } else {
                    float2 o = make_float2(ox, oy);
                    *reinterpret_cast<float2*>((float*)os.out[slot] + (size_t)gr * os.cpo + loc) = o;
                }
            }
        }
    }
}

// ======================= per-node attention aggregation =======================
template<int PER>
__device__ __forceinline__ void vloadh(float* r, const __half* __restrict__ p) {
    if constexpr (PER % 8 == 0) {
#pragma unroll
        for (int i = 0; i < PER / 8; i++) {
            uint4 t = reinterpret_cast<const uint4*>(p)[i];
            const __half2* h = reinterpret_cast<const __half2*>(&t);
#pragma unroll
            for (int j = 0; j < 4; j++) {
                float2 f = __half22float2(h[j]);
                r[i * 8 + j * 2 + 0] = f.x;
                r[i * 8 + j * 2 + 1] = f.y;
            }
        }
    } else {
        float2 f = __half22float2(*reinterpret_cast<const __half2*>(p));
        r[0] = f.x; r[1] = f.y;
    }
}

// One warp per destination node; 4-edge batch with K AND V gathered upfront as
// raw uint4 (MLP=16/lane, no false dependency of v-loads on softmax), lazy
// conversion at use. Online softmax; optional fused fp16 hi/lo split epilogue.
template<int HEADS, int CH, bool RELU, bool SPLIT>
__global__ void __launch_bounds__(256)
gat_agg_kernel(const __half* __restrict__ Q, const __half* __restrict__ Kf,
               const __half* __restrict__ V,
               const int* __restrict__ rowptr, const int* __restrict__ srcs,
               float* __restrict__ out,
               __half* __restrict__ hi, __half* __restrict__ lo, int n)
{
    constexpr int NCH = HEADS * CH;
    constexpr int PER = NCH / 32;
    constexpr int RW  = CH / PER;
    const int lane = threadIdx.x & 31;
    const int node = blockIdx.x * (blockDim.x >> 5) + (threadIdx.x >> 5);
    if (node >= n) return;

    const float scale = rsqrtf((float)CH);
    const size_t base = (size_t)node * NCH + lane * PER;

    float qv[PER], acc[PER];
    vloadh<PER>(qv, Q + base);
#pragma unroll
    for (int i = 0; i < PER; i++) acc[i] = 0.f;

    float m = __int_as_float(0xff800000);
    float s = 0.f;

    const int e0 = rowptr[node];
    const int e1 = rowptr[node + 1];
    int e = e0;

    if constexpr (PER % 8 == 0) {
        constexpr int NU = PER / 8;            // uint4s per row slice
        for (; e + 4 <= e1; e += 4) {
            size_t b[4];
#pragma unroll
            for (int j = 0; j < 4; j++)
                b[j] = (size_t)srcs[e + j] * NCH + lane * PER;

            // gather K and V for all 4 edges upfront (raw, no conversion)
            uint4 ku[4][NU], vu[4][NU];
#pragma unroll
            for (int j = 0; j < 4; j++) {
#pragma unroll
                for (int i = 0; i < NU; i++) {
                    ku[j][i] = reinterpret_cast<const uint4*>(Kf + b[j])[i];
                    vu[j][i] = reinterpret_cast<const uint4*>(V  + b[j])[i];
                }
            }

            float p[4];
#pragma unroll
            for (int j = 0; j < 4; j++) {
                float d = 0.f;
#pragma unroll
                for (int i = 0; i < NU; i++) {
                    const __half2* h = reinterpret_cast<const __half2*>(&ku[j][i]);
#pragma unroll
                    for (int t = 0; t < 4; t++) {
                        float2 f = __half22float2(h[t]);
                        d = fmaf(qv[i * 8 + t * 2 + 0], f.x, d);
                        d = fmaf(qv[i * 8 + t * 2 + 1], f.y, d);
                    }
                }
                p[j] = d;
            }
#pragma unroll
            for (int off = RW >> 1; off > 0; off >>= 1) {
#pragma unroll
                for (int j = 0; j < 4; j++)
                    p[j] += __shfl_xor_sync(0xffffffffu, p[j], off);
            }
            float w[4];
            const float a0 = p[0] * scale, a1 = p[1] * scale;
            const float a2 = p[2] * scale, a3 = p[3] * scale;
            const float mn = fmaxf(fmaxf(m, fmaxf(a0, a1)), fmaxf(a2, a3));
            const float corr = __expf(m - mn);
            w[0] = __expf(a0 - mn); w[1] = __expf(a1 - mn);
            w[2] = __expf(a2 - mn); w[3] = __expf(a3 - mn);
            s = s * corr + (w[0] + w[1]) + (w[2] + w[3]);

#pragma unroll
            for (int i = 0; i < PER; i++) acc[i] *= corr;
#pragma unroll
            for (int j = 0; j < 4; j++) {
                const float wj = w[j];
#pragma unroll
                for (int i = 0; i < NU; i++) {
                    const __half2* h = reinterpret_cast<const __half2*>(&vu[j][i]);
#pragma unroll
                    for (int t = 0; t < 4; t++) {
                        float2 f = __half22float2(h[t]);
                        acc[i * 8 + t * 2 + 0] = fmaf(wj, f.x, acc[i * 8 + t * 2 + 0]);
                        acc[i * 8 + t * 2 + 1] = fmaf(wj, f.y, acc[i * 8 + t * 2 + 1]);
                    }
                }
            }
            m = mn;
        }
    }
    for (; e < e1; e++) {
        const int sn = srcs[e];
        const size_t sbx = (size_t)sn * NCH + lane * PER;
        float kv[PER], vv[PER];
        vloadh<PER>(kv, Kf + sbx);
        vloadh<PER>(vv, V  + sbx);
        float part = 0.f;
#pragma unroll
        for (int i = 0; i < PER; i++) part = fmaf(qv[i], kv[i], part);
#pragma unroll
        for (int off = RW >> 1; off > 0; off >>= 1)
            part += __shfl_xor_sync(0xffffffffu, part, off);
        const float alpha = part * scale;
        const float mn = fmaxf(m, alpha);
        const float corr = __expf(m - mn);
        const float w = __expf(alpha - mn);
        s = s * corr + w;
#pragma unroll
        for (int i = 0; i < PER; i++) acc[i] = fmaf(acc[i], corr, w * vv[i]);
        m = mn;
    }

    const float inv = 1.f / (s + 1e-16f);
#pragma unroll
    for (int i = 0; i < PER; i++) {
        float o = out[base + i] + acc[i] * inv;
        if (RELU) o = fmaxf(o, 0.f);
        out[base + i] = o;
        if (SPLIT) {
            __half h = __float2half(o);
            hi[base + i] = h;
            lo[base + i] = __float2half(o - __half2float(h));
        }
    }
}

// ======================= host orchestration =======================
extern "C" void kernel_launch(void* const* d_in, const int* in_sizes, int n_in,
                              void* d_out, int out_size)
{
    const float* x  = (const float*)d_in[0];
    const void*  ei = d_in[1];
    const int N = in_sizes[0] / 128;
    const int E = in_sizes[1] / 2;

    const float* P[24];
    for (int i = 0; i < 24; i++) P[i] = (const float*)d_in[2 + i];

    float *h0, *h1, *biasf;
    __half *qh, *kh, *vh;
    __half *ahi, *alo, *whi, *wlo;
    int *rowptr, *cnt, *cur, *srcs;
    cudaGetSymbolAddress((void**)&qh, g_qh);
    cudaGetSymbolAddress((void**)&kh, g_kh);
    cudaGetSymbolAddress((void**)&vh, g_vh);
    cudaGetSymbolAddress((void**)&h0, g_h0);
    cudaGetSymbolAddress((void**)&h1, g_h1);
    cudaGetSymbolAddress((void**)&ahi, g_ahi);
    cudaGetSymbolAddress((void**)&alo, g_alo);
    cudaGetSymbolAddress((void**)&whi, g_whi);
    cudaGetSymbolAddress((void**)&wlo, g_wlo);
    cudaGetSymbolAddress((void**)&biasf, g_biasf);
    cudaGetSymbolAddress((void**)&rowptr, g_rowptr);
    cudaGetSymbolAddress((void**)&cnt, g_cnt);
    cudaGetSymbolAddress((void**)&cur, g_cur);
    cudaGetSymbolAddress((void**)&srcs, g_srcs);

    cudaFuncSetAttribute(gemm_mma_kernel, cudaFuncAttributeMaxDynamicSharedMemorySize, SMEM_TOT);

    // side stream + events (created once; never allocates device memory)
    static cudaStream_t s2 = nullptr;
    static cudaEvent_t evA = nullptr, evB = nullptr, evC = nullptr;
    if (!s2) {
        cudaStreamCreateWithFlags(&s2, cudaStreamNonBlocking);
        cudaEventCreateWithFlags(&evA, cudaEventDisableTiming);
        cudaEventCreateWithFlags(&evB, cudaEventDisableTiming);
        cudaEventCreateWithFlags(&evC, cudaEventDisableTiming);
    }

    const int TB = 256;
    float* out = (float*)d_out;

    WTable wt;
    const int Ks[3] = {128, 512, 512};
    const int Ms[3] = {512, 512, 64};
    for (int l = 0; l < 3; l++)
        for (int j = 0; j < 4; j++) {
            wt.d[l * 4 + j].W = P[l * 8 + j * 2];
            wt.d[l * 4 + j].b = P[l * 8 + j * 2 + 1];
            wt.d[l * 4 + j].K = Ks[l];
            wt.d[l * 4 + j].M = Ms[l];
            wt.d[l * 4 + j].layer = l;
            wt.d[l * 4 + j].off = j * Ms[l];
        }

    // layers 0/1: q,k,v tiles (0-11) 1-pass; skip tiles (12-15) 2-pass
    const uint32_t LP2_01 = 0xF000u;
    const uint32_t LP1_01 = 0x0FFFu;
    // layer 2 (2 tiles of 128): tile 0 = q+k -> 1-pass; tile 1 = v+skip -> 3-pass
    const uint32_t LP2_2 = 0x0u;
    const uint32_t LP1_2 = 0x1u;

    // ---- fork: CSR build + layer-1/2 weight prep on s2 ----
    detect_kernel<<<1, 128>>>((const int*)ei);
    cudaEventRecord(evA, 0);
    cudaStreamWaitEvent(s2, evA, 0);
    zero_int_kernel<<<(N + TB - 1) / TB, TB, 0, s2>>>(cnt, N);
    hist_kernel<<<(E + TB - 1) / TB, TB, 0, s2>>>(ei, cnt, E);
    scan_kernel<<<1, 1024, 0, s2>>>(cnt, rowptr, cur, N);
    scatter_kernel<<<(E + TB - 1) / TB, TB, 0, s2>>>(ei, cur, srcs, E);
    cudaEventRecord(evB, s2);
    prep_weights_kernel<<<dim3(64, 8), TB, 0, s2>>>(wt, 4, whi, wlo, biasf);
    cudaEventRecord(evC, s2);

    // main stream: layer-0 prep + GEMM-0
    prep_weights_kernel<<<dim3(64, 4), TB>>>(wt, 0, whi, wlo, biasf);
    split_act_kernel<<<(N * 128 + TB - 1) / TB, TB>>>(x, ahi, alo, N * 128);

    const int mtiles = (N + 127) / 128;
    OutSpec os0;
    os0.out[0] = qh; os0.out[1] = kh; os0.out[2] = vh; os0.out[3] = h0;
    os0.half_mask = 0b0111; os0.cpo = 512;
    gemm_mma_kernel<<<dim3(2048 / 128, mtiles), 256, SMEM_TOT>>>(
        ahi, alo, whi, wlo, biasf, os0, N, 128, LP2_01, LP1_01);

    cudaStreamWaitEvent(0, evB, 0);   // CSR ready before aggregation

    const int aggBlocks = (N + 7) / 8;
    gat_agg_kernel<8, 64, true, true><<<aggBlocks, 256>>>(
        qh, kh, vh, rowptr, srcs, h0, ahi, alo, N);

    cudaStreamWaitEvent(0, evC, 0);   // layer-1/2 weights ready

    // ---- layer 1 ----
    OutSpec os1;
    os1.out[0] = qh; os1.out[1] = kh; os1.out[2] = vh; os1.out[3] = h1;
    os1.half_mask = 0b0111; os1.cpo = 512;
    gemm_mma_kernel<<<dim3(2048 / 128, mtiles), 256, SMEM_TOT>>>(
        ahi, alo, whi + (size_t)1 * NTOTMAX * KMAX, wlo + (size_t)1 * NTOTMAX * KMAX,
        biasf + NTOTMAX, os1, N, 512, LP2_01, LP1_01);
    gat_agg_kernel<8, 64, true, true><<<aggBlocks, 256>>>(
        qh, kh, vh, rowptr, srcs, h1, ahi, alo, N);

    // ---- layer 2 (heads=1, ch=64) ----
    OutSpec os2;
    os2.out[0] = qh; os2.out[1] = kh; os2.out[2] = vh; os2.out[3] = out;
    os2.half_mask = 0b0111; os2.cpo = 64;
    gemm_mma_kernel<<<dim3(256 / 128, mtiles), 256, SMEM_TOT>>>(
        ahi, alo, whi + (size_t)2 * NTOTMAX * KMAX, wlo + (size_t)2 * NTOTMAX * KMAX,
        biasf + 2 * NTOTMAX, os2, N, 512, LP2_2, LP1_2);
    gat_agg_kernel<1, 64, false, false><<<aggBlocks, 256>>>(
        qh, kh, vh, rowptr, srcs, out, nullptr, nullptr, N);
}